// round 1
// baseline (speedup 1.0000x reference)
#include <cuda_runtime.h>
#include <math.h>

#define Bn 16
#define Ln 2048
#define Dn 512
#define En 8
#define Hn 8
#define HDn 64
#define EHn 64
#define Fn 2048

// -------- scratch (no allocation allowed) --------
__device__ float g_gates[Bn*En];
__device__ float g_xn[Bn*Dn];
__device__ float g_qh[Bn*En*Dn];
__device__ float g_qk[Bn*EHn*Dn];
__device__ float g_scores[Bn*EHn*Ln];   // 8 MB, overwritten with probs in-place
__device__ float g_ent[Bn*En];
__device__ float g_pr[Bn*EHn*Dn];
__device__ float g_attn[Bn*En*Dn];
__device__ float g_x[Bn*En*Dn];
__device__ float g_xo[Bn*En*Dn];
__device__ float g_h[Bn*En*Fn];

// K0: gating softmax + normalized query xn. grid=B, block=256
__global__ void k0_gate_ln(const float* __restrict__ query, const float* __restrict__ w_gate) {
    int b = blockIdx.x, t = threadIdx.x;
    __shared__ float q[Dn];
    __shared__ float red[256];
    __shared__ float lred[256*8];
    q[t] = query[b*Dn + t];
    q[t+256] = query[b*Dn + t + 256];
    __syncthreads();
    red[t] = q[t] + q[t+256];
    __syncthreads();
    for (int o = 128; o; o >>= 1) { if (t < o) red[t] += red[t+o]; __syncthreads(); }
    float mu = red[0] * (1.0f/Dn);
    __syncthreads();
    float d0 = q[t] - mu, d1 = q[t+256] - mu;
    red[t] = d0*d0 + d1*d1;
    __syncthreads();
    for (int o = 128; o; o >>= 1) { if (t < o) red[t] += red[t+o]; __syncthreads(); }
    float rstd = rsqrtf(red[0] * (1.0f/Dn) + 1e-5f);
    // gate logits: query @ w_gate (512x8)
    #pragma unroll
    for (int e = 0; e < 8; e++)
        lred[t*8+e] = q[t]*w_gate[t*8+e] + q[t+256]*w_gate[(t+256)*8+e];
    __syncthreads();
    for (int o = 128; o; o >>= 1) {
        if (t < o) {
            #pragma unroll
            for (int e = 0; e < 8; e++) lred[t*8+e] += lred[(t+o)*8+e];
        }
        __syncthreads();
    }
    if (t == 0) {
        float m = -1e30f;
        for (int e = 0; e < 8; e++) m = fmaxf(m, lred[e]);
        float s = 0.0f, ex[8];
        for (int e = 0; e < 8; e++) { ex[e] = expf(lred[e]-m); s += ex[e]; }
        for (int e = 0; e < 8; e++) g_gates[b*8+e] = ex[e]/s;
    }
    g_xn[b*Dn + t]       = d0*rstd;
    g_xn[b*Dn + t + 256] = d1*rstd;
}

// K1: qh[b,e,k] = (xn*g_e+b_e) @ Wq[e] + bq[e].  grid=(8 ktiles,E), block=256 (4 dgroups x 64 lanes)
__global__ void k1_qh(const float* __restrict__ ln_q_g, const float* __restrict__ ln_q_b,
                      const float* __restrict__ Wq, const float* __restrict__ bq) {
    int e = blockIdx.y, k0 = blockIdx.x*64;
    int t = threadIdx.x, g = t >> 6, kl = t & 63;
    int k = k0 + kl;
    __shared__ float qn[Bn][Dn];
    __shared__ float red[4][Bn][64];
    for (int i = t; i < Bn*Dn; i += 256) {
        int b = i >> 9, d = i & 511;
        qn[b][d] = g_xn[b*Dn+d]*ln_q_g[e*Dn+d] + ln_q_b[e*Dn+d];
    }
    __syncthreads();
    float acc[Bn];
    #pragma unroll
    for (int b = 0; b < Bn; b++) acc[b] = 0.0f;
    const float* W = Wq + (size_t)e*Dn*Dn + k;
    for (int d = g*128; d < g*128+128; d++) {
        float w = W[(size_t)d*Dn];
        #pragma unroll
        for (int b = 0; b < Bn; b++) acc[b] = fmaf(qn[b][d], w, acc[b]);
    }
    #pragma unroll
    for (int b = 0; b < Bn; b++) red[g][b][kl] = acc[b];
    __syncthreads();
    for (int i = t; i < Bn*64; i += 256) {
        int b = i >> 6, k2 = i & 63;
        float s = red[0][b][k2]+red[1][b][k2]+red[2][b][k2]+red[3][b][k2];
        g_qh[(b*En+e)*Dn + k0 + k2] = s + bq[e*Dn + k0 + k2];
    }
}

// K2: qk[b,eh,d] = (sum_c qh[b,e,h*64+c]*Wk[e,d,h*64+c]) * (1/sqrt(HD)).  grid=EH, block=256
__global__ void k2_qk(const float* __restrict__ Wk) {
    int eh = blockIdx.x, e = eh >> 3, h = eh & 7;
    int t = threadIdx.x;
    __shared__ float qs[Bn][HDn];
    for (int i = t; i < Bn*HDn; i += 256) {
        int b = i >> 6, c = i & 63;
        qs[b][c] = g_qh[(b*En+e)*Dn + h*HDn + c];
    }
    __syncthreads();
    #pragma unroll
    for (int dd = 0; dd < 2; dd++) {
        int d = t + dd*256;
        const float4* W4 = (const float4*)(Wk + (size_t)e*Dn*Dn + (size_t)d*Dn + h*HDn);
        float acc[Bn];
        #pragma unroll
        for (int b = 0; b < Bn; b++) acc[b] = 0.0f;
        #pragma unroll
        for (int c4 = 0; c4 < 16; c4++) {
            float4 w = W4[c4];
            int c = c4*4;
            #pragma unroll
            for (int b = 0; b < Bn; b++) {
                acc[b] = fmaf(qs[b][c],   w.x, acc[b]);
                acc[b] = fmaf(qs[b][c+1], w.y, acc[b]);
                acc[b] = fmaf(qs[b][c+2], w.z, acc[b]);
                acc[b] = fmaf(qs[b][c+3], w.w, acc[b]);
            }
        }
        #pragma unroll
        for (int b = 0; b < Bn; b++) g_qk[(b*EHn+eh)*Dn + d] = acc[b]*0.125f;
    }
}

// K3: scores[b,eh,l] = R[b,l,:] . qk[b,eh,:]   (per-b GEMM 2048x512 @ 512x64)
// grid=(32 ltiles, B), block=256 (16x16, 4x4 micro)
__global__ void k3_scores(const float* __restrict__ R) {
    int b = blockIdx.y, l0 = blockIdx.x*64;
    int t = threadIdx.x, tx = t & 15, ty = t >> 4;
    __shared__ float As[32][65];
    __shared__ float Bs[32][65];
    __shared__ float Cs[64][65];
    float acc[4][4] = {};
    for (int d0 = 0; d0 < Dn; d0 += 32) {
        for (int i = t; i < 2048; i += 256) {
            int l = i >> 5, kk = i & 31;
            As[kk][l] = R[(b*Ln + l0 + l)*Dn + d0 + kk];
            Bs[kk][l] = g_qk[(b*EHn + l)*Dn + d0 + kk];   // l plays eh role (both 64)
        }
        __syncthreads();
        #pragma unroll
        for (int kk = 0; kk < 32; kk++) {
            float a[4], bb[4];
            #pragma unroll
            for (int i = 0; i < 4; i++) a[i] = As[kk][ty*4+i];
            #pragma unroll
            for (int j = 0; j < 4; j++) bb[j] = Bs[kk][tx*4+j];
            #pragma unroll
            for (int i = 0; i < 4; i++)
                #pragma unroll
                for (int j = 0; j < 4; j++) acc[i][j] = fmaf(a[i], bb[j], acc[i][j]);
        }
        __syncthreads();
    }
    #pragma unroll
    for (int i = 0; i < 4; i++)
        #pragma unroll
        for (int j = 0; j < 4; j++) Cs[tx*4+j][ty*4+i] = acc[i][j];
    __syncthreads();
    for (int i = t; i < 4096; i += 256) {
        int eh = i >> 6, l = i & 63;
        g_scores[(b*EHn + eh)*Ln + l0 + l] = Cs[eh][l];
    }
}

// K4: softmax over L per (b,e,h) in-place + head-averaged entropy. grid=B*E, block=256
__global__ void k4_softmax() {
    int be = blockIdx.x;       // b*E+e
    int t = threadIdx.x;
    __shared__ float avg[Ln];
    __shared__ float red[256];
    for (int i = t; i < Ln; i += 256) avg[i] = 0.0f;
    __syncthreads();
    float* base = g_scores + (size_t)be*Hn*Ln;
    for (int h = 0; h < Hn; h++) {
        float* src = base + (size_t)h*Ln;
        float v[8];
        float lm = -1e30f;
        #pragma unroll
        for (int r = 0; r < 8; r++) { v[r] = src[t + r*256]; lm = fmaxf(lm, v[r]); }
        red[t] = lm; __syncthreads();
        for (int o = 128; o; o >>= 1) { if (t < o) red[t] = fmaxf(red[t], red[t+o]); __syncthreads(); }
        float m = red[0]; __syncthreads();
        float ls = 0.0f;
        #pragma unroll
        for (int r = 0; r < 8; r++) { v[r] = expf(v[r]-m); ls += v[r]; }
        red[t] = ls; __syncthreads();
        for (int o = 128; o; o >>= 1) { if (t < o) red[t] += red[t+o]; __syncthreads(); }
        float inv = 1.0f/red[0]; __syncthreads();
        #pragma unroll
        for (int r = 0; r < 8; r++) {
            float p = v[r]*inv;
            src[t + r*256] = p;
            avg[t + r*256] += p*0.125f;
        }
        __syncthreads();
    }
    float lent = 0.0f;
    for (int i = t; i < Ln; i += 256) {
        float p = fmaxf(avg[i], 1e-12f);
        lent -= p*logf(p);
    }
    red[t] = lent; __syncthreads();
    for (int o = 128; o; o >>= 1) { if (t < o) red[t] += red[t+o]; __syncthreads(); }
    if (t == 0) g_ent[be] = red[0];
}

// K5: pr[b,eh,d] = probs[b,eh,:] @ R[b,:,d]   (per-b GEMM 64x2048 @ 2048x512)
// grid=(8 dtiles, B), block=256
__global__ void k5_pr(const float* __restrict__ R) {
    int b = blockIdx.y, d0 = blockIdx.x*64;
    int t = threadIdx.x, tx = t & 15, ty = t >> 4;
    __shared__ float As[32][65];
    __shared__ float Bs[32][65];
    __shared__ float Cs[64][65];
    float acc[4][4] = {};
    for (int l0 = 0; l0 < Ln; l0 += 32) {
        for (int i = t; i < 2048; i += 256) {
            int eh = i >> 5, kk = i & 31;
            As[kk][eh] = g_scores[((size_t)b*EHn + eh)*Ln + l0 + kk];
            int kk2 = i >> 6, dd = i & 63;
            Bs[kk2][dd] = R[(b*Ln + l0 + kk2)*Dn + d0 + dd];
        }
        __syncthreads();
        #pragma unroll
        for (int kk = 0; kk < 32; kk++) {
            float a[4], bb[4];
            #pragma unroll
            for (int i = 0; i < 4; i++) a[i] = As[kk][ty*4+i];
            #pragma unroll
            for (int j = 0; j < 4; j++) bb[j] = Bs[kk][tx*4+j];
            #pragma unroll
            for (int i = 0; i < 4; i++)
                #pragma unroll
                for (int j = 0; j < 4; j++) acc[i][j] = fmaf(a[i], bb[j], acc[i][j]);
        }
        __syncthreads();
    }
    #pragma unroll
    for (int i = 0; i < 4; i++)
        #pragma unroll
        for (int j = 0; j < 4; j++) Cs[ty*4+i][tx*4+j] = acc[i][j];
    __syncthreads();
    for (int i = t; i < 4096; i += 256) {
        int eh = i >> 6, dd = i & 63;
        g_pr[(b*EHn + eh)*Dn + d0 + dd] = Cs[eh][dd];
    }
}

// K6a: attn[b,e,h*64+c] = pr[b,eh,:] @ Wv[e,:,h*64+c] + bv. grid=EH, block=256 (4 dgroups x 64 c)
__global__ void k6a_attn(const float* __restrict__ Wv, const float* __restrict__ bv) {
    int eh = blockIdx.x, e = eh >> 3, h = eh & 7;
    int t = threadIdx.x, g = t >> 6, c = t & 63;
    __shared__ float ps[Bn][Dn];
    __shared__ float red[4][Bn][64];
    for (int i = t; i < Bn*Dn; i += 256) {
        int b = i >> 9, d = i & 511;
        ps[b][d] = g_pr[(b*EHn+eh)*Dn + d];
    }
    __syncthreads();
    float acc[Bn];
    #pragma unroll
    for (int b = 0; b < Bn; b++) acc[b] = 0.0f;
    const float* W = Wv + (size_t)e*Dn*Dn + h*HDn + c;
    for (int d = g*128; d < g*128+128; d++) {
        float w = W[(size_t)d*Dn];
        #pragma unroll
        for (int b = 0; b < Bn; b++) acc[b] = fmaf(ps[b][d], w, acc[b]);
    }
    #pragma unroll
    for (int b = 0; b < Bn; b++) red[g][b][c] = acc[b];
    __syncthreads();
    for (int i = t; i < Bn*64; i += 256) {
        int b = i >> 6, cc = i & 63;
        float s = red[0][b][cc]+red[1][b][cc]+red[2][b][cc]+red[3][b][cc];
        g_attn[(b*En+e)*Dn + h*HDn + cc] = s + bv[e*Dn + h*HDn + cc];
    }
}

// K6b: x = query + attn @ Wo + bo.  grid=(8 ktiles, E), block=256
__global__ void k6b_attnout(const float* __restrict__ Wo, const float* __restrict__ bo,
                            const float* __restrict__ query) {
    int e = blockIdx.y, k0 = blockIdx.x*64;
    int t = threadIdx.x, g = t >> 6, kl = t & 63;
    int k = k0 + kl;
    __shared__ float as_[Bn][Dn];
    __shared__ float red[4][Bn][64];
    for (int i = t; i < Bn*Dn; i += 256) {
        int b = i >> 9, d = i & 511;
        as_[b][d] = g_attn[(b*En+e)*Dn + d];
    }
    __syncthreads();
    float acc[Bn];
    #pragma unroll
    for (int b = 0; b < Bn; b++) acc[b] = 0.0f;
    const float* W = Wo + (size_t)e*Dn*Dn + k;
    for (int d = g*128; d < g*128+128; d++) {
        float w = W[(size_t)d*Dn];
        #pragma unroll
        for (int b = 0; b < Bn; b++) acc[b] = fmaf(as_[b][d], w, acc[b]);
    }
    #pragma unroll
    for (int b = 0; b < Bn; b++) red[g][b][kl] = acc[b];
    __syncthreads();
    for (int i = t; i < Bn*64; i += 256) {
        int b = i >> 6, k2 = i & 63;
        float s = red[0][b][k2]+red[1][b][k2]+red[2][b][k2]+red[3][b][k2];
        g_x[(b*En+e)*Dn + k0+k2] = s + bo[e*Dn + k0+k2] + query[b*Dn + k0+k2];
    }
}

// LN of x -> xo. grid=B*E, block=256
__global__ void k_ln2(const float* __restrict__ ln_o_g, const float* __restrict__ ln_o_b) {
    int be = blockIdx.x, e = be & 7;
    int t = threadIdx.x;
    __shared__ float red[256];
    const float* x = g_x + (size_t)be*Dn;
    float v0 = x[t], v1 = x[t+256];
    red[t] = v0 + v1; __syncthreads();
    for (int o = 128; o; o >>= 1) { if (t < o) red[t] += red[t+o]; __syncthreads(); }
    float mu = red[0]*(1.0f/Dn); __syncthreads();
    float d0 = v0-mu, d1 = v1-mu;
    red[t] = d0*d0 + d1*d1; __syncthreads();
    for (int o = 128; o; o >>= 1) { if (t < o) red[t] += red[t+o]; __syncthreads(); }
    float rstd = rsqrtf(red[0]*(1.0f/Dn) + 1e-5f);
    g_xo[be*Dn + t]     = d0*rstd*ln_o_g[e*Dn+t]     + ln_o_b[e*Dn+t];
    g_xo[be*Dn + t+256] = d1*rstd*ln_o_g[e*Dn+t+256] + ln_o_b[e*Dn+t+256];
}

// K7: h = gelu(xo @ W1 + b1). grid=(32 ftiles, E), block=256
__global__ void k7_ffn1(const float* __restrict__ W1, const float* __restrict__ b1) {
    int e = blockIdx.y, f0 = blockIdx.x*64;
    int t = threadIdx.x, g = t >> 6, fl = t & 63;
    int f = f0 + fl;
    __shared__ float xs[Bn][Dn];
    __shared__ float red[4][Bn][64];
    for (int i = t; i < Bn*Dn; i += 256) {
        int b = i >> 9, d = i & 511;
        xs[b][d] = g_xo[(b*En+e)*Dn + d];
    }
    __syncthreads();
    float acc[Bn];
    #pragma unroll
    for (int b = 0; b < Bn; b++) acc[b] = 0.0f;
    const float* W = W1 + (size_t)e*Dn*Fn + f;
    for (int d = g*128; d < g*128+128; d++) {
        float w = W[(size_t)d*Fn];
        #pragma unroll
        for (int b = 0; b < Bn; b++) acc[b] = fmaf(xs[b][d], w, acc[b]);
    }
    #pragma unroll
    for (int b = 0; b < Bn; b++) red[g][b][fl] = acc[b];
    __syncthreads();
    for (int i = t; i < Bn*64; i += 256) {
        int b = i >> 6, ff = i & 63;
        float v = red[0][b][ff]+red[1][b][ff]+red[2][b][ff]+red[3][b][ff] + b1[e*Fn + f0+ff];
        v = 0.5f*v*(1.0f + erff(v*0.70710678118654752f));   // exact gelu
        g_h[(b*En+e)*Fn + f0+ff] = v;
    }
}

// K8: y = h @ W2 + b2 + x  (written straight to out y-region). grid=(8 ktiles, E), block=256
__global__ void k8_ffn2(const float* __restrict__ W2, const float* __restrict__ b2,
                        float* __restrict__ y_out) {
    int e = blockIdx.y, k0 = blockIdx.x*64;
    int t = threadIdx.x, g = t >> 6, kl = t & 63;
    int k = k0 + kl;
    __shared__ float hs[4][Bn][64];
    __shared__ float red[4][Bn][64];
    float acc[Bn];
    #pragma unroll
    for (int b = 0; b < Bn; b++) acc[b] = 0.0f;
    for (int sub = 0; sub < 8; sub++) {
        int fbase = g*512 + sub*64;
        #pragma unroll
        for (int b = 0; b < Bn; b++)
            hs[g][b][kl] = g_h[(b*En+e)*Fn + fbase + kl];
        __syncthreads();
        const float* W = W2 + (size_t)e*Fn*Dn + (size_t)fbase*Dn + k;
        for (int ff = 0; ff < 64; ff++) {
            float w = W[(size_t)ff*Dn];
            #pragma unroll
            for (int b = 0; b < Bn; b++) acc[b] = fmaf(hs[g][b][ff], w, acc[b]);
        }
        __syncthreads();
    }
    #pragma unroll
    for (int b = 0; b < Bn; b++) red[g][b][kl] = acc[b];
    __syncthreads();
    for (int i = t; i < Bn*64; i += 256) {
        int b = i >> 6, k2 = i & 63;
        float v = red[0][b][k2]+red[1][b][k2]+red[2][b][k2]+red[3][b][k2]
                + b2[e*Dn + k0+k2] + g_x[(b*En+e)*Dn + k0+k2];
        y_out[(b*En+e)*Dn + k0+k2] = v;
    }
}

// K9: reliability weights, mixture, outputs. grid=B, block=512
__global__ void k9_final(float* __restrict__ out) {
    int b = blockIdx.x, t = threadIdx.x;
    __shared__ float gt[8];
    if (t < 8) gt[t] = g_gates[b*8+t]*expf(-0.5f*g_ent[b*8+t]);
    __syncthreads();
    if (t == 0) {
        float s = 0.0f;
        for (int e = 0; e < 8; e++) s += gt[e];
        float inv = 1.0f/(s + 1e-9f);
        for (int e = 0; e < 8; e++) gt[e] *= inv;
    }
    __syncthreads();
    if (t < 8) out[Bn*Dn + Bn*En*Dn + b*8 + t] = gt[t];   // gt region
    const float* y = out + Bn*Dn;                          // y region
    float m = 0.0f;
    #pragma unroll
    for (int e = 0; e < 8; e++) m = fmaf(gt[e], y[(b*En+e)*Dn + t], m);
    out[b*Dn + t] = m;   // ALPHA=1 -> fused = mixture
}

extern "C" void kernel_launch(void* const* d_in, const int* in_sizes, int n_in,
                              void* d_out, int out_size) {
    const float* query     = (const float*)d_in[0];
    const float* retrieved = (const float*)d_in[1];
    const float* w_gate    = (const float*)d_in[2];
    const float* ln_q_g    = (const float*)d_in[3];
    const float* ln_q_b    = (const float*)d_in[4];
    const float* Wq        = (const float*)d_in[5];
    const float* bq        = (const float*)d_in[6];
    const float* Wk        = (const float*)d_in[7];
    /* d_in[8] = bk: provably cancels in softmax, unused */
    const float* Wv        = (const float*)d_in[9];
    const float* bv        = (const float*)d_in[10];
    const float* Wo        = (const float*)d_in[11];
    const float* bo        = (const float*)d_in[12];
    const float* ln_o_g    = (const float*)d_in[13];
    const float* ln_o_b    = (const float*)d_in[14];
    const float* W1        = (const float*)d_in[15];
    const float* b1        = (const float*)d_in[16];
    const float* W2        = (const float*)d_in[17];
    const float* b2        = (const float*)d_in[18];
    float* out = (float*)d_out;

    k0_gate_ln<<<Bn, 256>>>(query, w_gate);
    k1_qh<<<dim3(8, En), 256>>>(ln_q_g, ln_q_b, Wq, bq);
    k2_qk<<<EHn, 256>>>(Wk);
    k3_scores<<<dim3(32, Bn), 256>>>(retrieved);
    k4_softmax<<<Bn*En, 256>>>();
    k5_pr<<<dim3(8, Bn), 256>>>(retrieved);
    k6a_attn<<<EHn, 256>>>(Wv, bv);
    k6b_attnout<<<dim3(8, En), 256>>>(Wo, bo, query);
    k_ln2<<<Bn*En, 256>>>(ln_o_g, ln_o_b);
    k7_ffn1<<<dim3(32, En), 256>>>(W1, b1);
    k8_ffn2<<<dim3(8, En), 256>>>(W2, b2, out + Bn*Dn);
    k9_final<<<Bn, 512>>>(out);
}

// round 2
// speedup vs baseline: 1.4776x; 1.4776x over previous
#include <cuda_runtime.h>
#include <math.h>

#define Bn 16
#define Ln 2048
#define Dn 512
#define En 8
#define Hn 8
#define HDn 64
#define EHn 64
#define Fn 2048

typedef unsigned long long ull;

// -------- scratch --------
__device__ float g_gates[Bn*En];
__device__ float g_xn[Bn*Dn];
__device__ float g_qh[Bn*En*Dn];
__device__ float g_qk[Bn*EHn*Dn];
__device__ float g_scores[Bn*EHn*Ln];      // 8 MB, becomes probs in place
__device__ float g_ent[Bn*En];
__device__ float g_prp[4*Bn*EHn*Dn];       // k-split partials of probs@R
__device__ float g_attn[Bn*En*Dn];
__device__ float g_x[Bn*En*Dn];
__device__ float g_xo[Bn*En*Dn];
__device__ float g_h[Bn*En*Fn];
__device__ float g_y4[4*Bn*En*Dn];         // FFN2 f-split partials

__device__ __forceinline__ void fma2(ull &c, ull a, ull b) {
    asm("fma.rn.f32x2 %0, %1, %2, %0;" : "+l"(c) : "l"(a), "l"(b));
}

// K0: gating softmax + normalized query xn. grid=B, block=256
__global__ void k0_gate_ln(const float* __restrict__ query, const float* __restrict__ w_gate) {
    int b = blockIdx.x, t = threadIdx.x;
    __shared__ float q[Dn];
    __shared__ float red[256];
    __shared__ float lred[256*8];
    q[t] = query[b*Dn + t];
    q[t+256] = query[b*Dn + t + 256];
    __syncthreads();
    red[t] = q[t] + q[t+256];
    __syncthreads();
    for (int o = 128; o; o >>= 1) { if (t < o) red[t] += red[t+o]; __syncthreads(); }
    float mu = red[0] * (1.0f/Dn);
    __syncthreads();
    float d0 = q[t] - mu, d1 = q[t+256] - mu;
    red[t] = d0*d0 + d1*d1;
    __syncthreads();
    for (int o = 128; o; o >>= 1) { if (t < o) red[t] += red[t+o]; __syncthreads(); }
    float rstd = rsqrtf(red[0] * (1.0f/Dn) + 1e-5f);
    #pragma unroll
    for (int e = 0; e < 8; e++)
        lred[t*8+e] = q[t]*w_gate[t*8+e] + q[t+256]*w_gate[(t+256)*8+e];
    __syncthreads();
    for (int o = 128; o; o >>= 1) {
        if (t < o) {
            #pragma unroll
            for (int e = 0; e < 8; e++) lred[t*8+e] += lred[(t+o)*8+e];
        }
        __syncthreads();
    }
    if (t == 0) {
        float m = -1e30f;
        for (int e = 0; e < 8; e++) m = fmaxf(m, lred[e]);
        float s = 0.0f, ex[8];
        for (int e = 0; e < 8; e++) { ex[e] = expf(lred[e]-m); s += ex[e]; }
        for (int e = 0; e < 8; e++) g_gates[b*8+e] = ex[e]/s;
    }
    g_xn[b*Dn + t]       = d0*rstd;
    g_xn[b*Dn + t + 256] = d1*rstd;
}

// K1: qh = (xn*g_e+b_e) @ Wq[e] + bq[e].  grid=(8,E), block=256
__global__ void k1_qh(const float* __restrict__ ln_q_g, const float* __restrict__ ln_q_b,
                      const float* __restrict__ Wq, const float* __restrict__ bq) {
    int e = blockIdx.y, k0 = blockIdx.x*64;
    int t = threadIdx.x, g = t >> 6, kl = t & 63;
    int k = k0 + kl;
    __shared__ float qn[Bn][Dn];
    for (int i = t; i < Bn*Dn; i += 256) {
        int b = i >> 9, d = i & 511;
        qn[b][d] = g_xn[b*Dn+d]*ln_q_g[e*Dn+d] + ln_q_b[e*Dn+d];
    }
    __syncthreads();
    float acc[Bn];
    #pragma unroll
    for (int b = 0; b < Bn; b++) acc[b] = 0.0f;
    const float* W = Wq + (size_t)e*Dn*Dn + k;
    for (int d = g*128; d < g*128+128; d += 4) {
        float w0 = W[(size_t)(d+0)*Dn];
        float w1 = W[(size_t)(d+1)*Dn];
        float w2 = W[(size_t)(d+2)*Dn];
        float w3 = W[(size_t)(d+3)*Dn];
        #pragma unroll
        for (int b = 0; b < Bn; b++) {
            float4 q4 = *(const float4*)&qn[b][d];
            acc[b] = fmaf(q4.x, w0, acc[b]);
            acc[b] = fmaf(q4.y, w1, acc[b]);
            acc[b] = fmaf(q4.z, w2, acc[b]);
            acc[b] = fmaf(q4.w, w3, acc[b]);
        }
    }
    __syncthreads();
    float* red = &qn[0][0];   // reuse smem
    #pragma unroll
    for (int b = 0; b < Bn; b++) red[(g*Bn + b)*64 + kl] = acc[b];
    __syncthreads();
    for (int i = t; i < Bn*64; i += 256) {
        int b = i >> 6, k2 = i & 63;
        float s = red[(0*Bn+b)*64+k2]+red[(1*Bn+b)*64+k2]+red[(2*Bn+b)*64+k2]+red[(3*Bn+b)*64+k2];
        g_qh[(b*En+e)*Dn + k0 + k2] = s + bq[e*Dn + k0 + k2];
    }
}

// K2: qk[b,eh,d] = (sum_c qh[b,e,h*64+c]*Wk[e,d,h*64+c]) * (1/sqrt(HD)). grid=EH, block=256
__global__ void k2_qk(const float* __restrict__ Wk) {
    int eh = blockIdx.x, e = eh >> 3, h = eh & 7;
    int t = threadIdx.x;
    __shared__ float qs[Bn][HDn];
    for (int i = t; i < Bn*HDn; i += 256) {
        int b = i >> 6, c = i & 63;
        qs[b][c] = g_qh[(b*En+e)*Dn + h*HDn + c];
    }
    __syncthreads();
    #pragma unroll
    for (int dd = 0; dd < 2; dd++) {
        int d = t + dd*256;
        const float4* W4 = (const float4*)(Wk + (size_t)e*Dn*Dn + (size_t)d*Dn + h*HDn);
        float acc[Bn];
        #pragma unroll
        for (int b = 0; b < Bn; b++) acc[b] = 0.0f;
        #pragma unroll
        for (int c4 = 0; c4 < 16; c4++) {
            float4 w = W4[c4];
            int c = c4*4;
            #pragma unroll
            for (int b = 0; b < Bn; b++) {
                acc[b] = fmaf(qs[b][c],   w.x, acc[b]);
                acc[b] = fmaf(qs[b][c+1], w.y, acc[b]);
                acc[b] = fmaf(qs[b][c+2], w.z, acc[b]);
                acc[b] = fmaf(qs[b][c+3], w.w, acc[b]);
            }
        }
        #pragma unroll
        for (int b = 0; b < Bn; b++) g_qk[(b*EHn+eh)*Dn + d] = acc[b]*0.125f;
    }
}

// K3: scores = R @ qk^T per b. Tile 256(l) x 64(eh), K=512, micro 8x8 via f32x2.
// grid=(8, B), block=256. tx=t&31 -> l=tx*8, ty=t>>5 -> eh=ty*8.
__global__ void __launch_bounds__(256) k3_scores(const float* __restrict__ R) {
    int b = blockIdx.y, l0 = blockIdx.x*256;
    int t = threadIdx.x, tx = t & 31, ty = t >> 5;
    __shared__ float As[16][260];       // [kk][l]
    __shared__ float2 Bd2[16][66];      // [kk][eh], duplicated pairs
    ull acc[8][4];
    #pragma unroll
    for (int i = 0; i < 8; i++)
        #pragma unroll
        for (int j = 0; j < 4; j++) acc[i][j] = 0ull;

    const float* Rrow = R + ((size_t)b*Ln + l0 + t)*Dn;
    int ehL = t >> 2, kkb = (t & 3)*4;
    const float* Qrow = g_qk + ((size_t)b*EHn + ehL)*Dn + kkb;

    float4 aR0 = *(const float4*)&Rrow[0];
    float4 aR1 = *(const float4*)&Rrow[4];
    float4 aR2 = *(const float4*)&Rrow[8];
    float4 aR3 = *(const float4*)&Rrow[12];
    float4 bQ  = *(const float4*)&Qrow[0];

    for (int s = 0; s < 32; s++) {
        __syncthreads();
        As[0][t]=aR0.x; As[1][t]=aR0.y; As[2][t]=aR0.z; As[3][t]=aR0.w;
        As[4][t]=aR1.x; As[5][t]=aR1.y; As[6][t]=aR1.z; As[7][t]=aR1.w;
        As[8][t]=aR2.x; As[9][t]=aR2.y; As[10][t]=aR2.z; As[11][t]=aR2.w;
        As[12][t]=aR3.x; As[13][t]=aR3.y; As[14][t]=aR3.z; As[15][t]=aR3.w;
        Bd2[kkb+0][ehL] = make_float2(bQ.x, bQ.x);
        Bd2[kkb+1][ehL] = make_float2(bQ.y, bQ.y);
        Bd2[kkb+2][ehL] = make_float2(bQ.z, bQ.z);
        Bd2[kkb+3][ehL] = make_float2(bQ.w, bQ.w);
        __syncthreads();
        if (s+1 < 32) {
            int d0 = (s+1)*16;
            aR0 = *(const float4*)&Rrow[d0+0];
            aR1 = *(const float4*)&Rrow[d0+4];
            aR2 = *(const float4*)&Rrow[d0+8];
            aR3 = *(const float4*)&Rrow[d0+12];
            bQ  = *(const float4*)&Qrow[d0];
        }
        #pragma unroll
        for (int kk = 0; kk < 16; kk++) {
            ulonglong2 a01 = *(const ulonglong2*)&As[kk][tx*8];
            ulonglong2 a23 = *(const ulonglong2*)&As[kk][tx*8+4];
            ulonglong2 b01 = *(const ulonglong2*)&Bd2[kk][ty*8];
            ulonglong2 b23 = *(const ulonglong2*)&Bd2[kk][ty*8+2];
            ulonglong2 b45 = *(const ulonglong2*)&Bd2[kk][ty*8+4];
            ulonglong2 b67 = *(const ulonglong2*)&Bd2[kk][ty*8+6];
            ull av[4] = {a01.x, a01.y, a23.x, a23.y};
            ull bv[8] = {b01.x, b01.y, b23.x, b23.y, b45.x, b45.y, b67.x, b67.y};
            #pragma unroll
            for (int i = 0; i < 8; i++)
                #pragma unroll
                for (int j = 0; j < 4; j++) fma2(acc[i][j], bv[i], av[j]);
        }
    }
    #pragma unroll
    for (int i = 0; i < 8; i++) {
        int eh = ty*8 + i;
        float2* dst = (float2*)&g_scores[((size_t)b*EHn + eh)*Ln + l0 + tx*8];
        #pragma unroll
        for (int j = 0; j < 4; j++) dst[j] = *(float2*)&acc[i][j];
    }
}

// K4: softmax per (b,e,h) warp-per-head + entropy. grid=B*E, block=256
__global__ void k4_softmax() {
    int be = blockIdx.x;
    int t = threadIdx.x, w = t >> 5, lane = t & 31;
    __shared__ float red[256];
    float* base = g_scores + (size_t)be*Hn*Ln;
    float* src = base + (size_t)w*Ln;
    float4 v[16];
    float m = -1e30f;
    #pragma unroll
    for (int i = 0; i < 16; i++) {
        v[i] = *(const float4*)&src[(i*32 + lane)*4];
        m = fmaxf(m, fmaxf(fmaxf(v[i].x, v[i].y), fmaxf(v[i].z, v[i].w)));
    }
    #pragma unroll
    for (int o = 16; o; o >>= 1) m = fmaxf(m, __shfl_xor_sync(0xffffffffu, m, o));
    float s = 0.0f;
    #pragma unroll
    for (int i = 0; i < 16; i++) {
        v[i].x = __expf(v[i].x - m); v[i].y = __expf(v[i].y - m);
        v[i].z = __expf(v[i].z - m); v[i].w = __expf(v[i].w - m);
        s += v[i].x + v[i].y + v[i].z + v[i].w;
    }
    #pragma unroll
    for (int o = 16; o; o >>= 1) s += __shfl_xor_sync(0xffffffffu, s, o);
    float inv = 1.0f/s;
    #pragma unroll
    for (int i = 0; i < 16; i++) {
        v[i].x *= inv; v[i].y *= inv; v[i].z *= inv; v[i].w *= inv;
        *(float4*)&src[(i*32 + lane)*4] = v[i];
    }
    __syncthreads();   // probs of all 8 heads visible block-wide
    float lent = 0.0f;
    for (int i = t; i < Ln; i += 256) {
        float s8 = 0.0f;
        #pragma unroll
        for (int h = 0; h < 8; h++) s8 += base[h*Ln + i];
        float p = fmaxf(s8*0.125f, 1e-12f);
        lent -= p*__logf(p);
    }
    red[t] = lent; __syncthreads();
    for (int o = 128; o; o >>= 1) { if (t < o) red[t] += red[t+o]; __syncthreads(); }
    if (t == 0) g_ent[be] = red[0];
}

// K5: pr_partial[ks] = probs[:, ks*512:(ks+1)*512] @ R-chunk. Tile 64(eh) x 256(d).
// grid=(2 dtiles, B, 4 ks), block=256. tx=t&31 -> d=tx*8, ty=t>>5 -> eh=ty*8.
__global__ void __launch_bounds__(256) k5_pr(const float* __restrict__ R) {
    int b = blockIdx.y, d0base = blockIdx.x*256, ks = blockIdx.z;
    int t = threadIdx.x, tx = t & 31, ty = t >> 5;
    __shared__ float Bs[16][260];       // [kk][d]
    __shared__ float2 Ad2[16][66];      // [kk][eh] duplicated
    ull acc[8][4];
    #pragma unroll
    for (int i = 0; i < 8; i++)
        #pragma unroll
        for (int j = 0; j < 4; j++) acc[i][j] = 0ull;

    int ehL = t >> 2, kkbA = (t & 3)*4;
    const float* Prow = g_scores + ((size_t)b*EHn + ehL)*Ln + ks*512 + kkbA;
    int kkB = t >> 4, dseg = (t & 15)*16;
    const float* Rrow = R + ((size_t)b*Ln + ks*512 + kkB)*Dn + d0base + dseg;

    float4 aP = *(const float4*)&Prow[0];
    float4 bR0 = *(const float4*)&Rrow[0];
    float4 bR1 = *(const float4*)&Rrow[4];
    float4 bR2 = *(const float4*)&Rrow[8];
    float4 bR3 = *(const float4*)&Rrow[12];

    for (int s = 0; s < 32; s++) {
        __syncthreads();
        Ad2[kkbA+0][ehL] = make_float2(aP.x, aP.x);
        Ad2[kkbA+1][ehL] = make_float2(aP.y, aP.y);
        Ad2[kkbA+2][ehL] = make_float2(aP.z, aP.z);
        Ad2[kkbA+3][ehL] = make_float2(aP.w, aP.w);
        *(float4*)&Bs[kkB][dseg+0]  = bR0;
        *(float4*)&Bs[kkB][dseg+4]  = bR1;
        *(float4*)&Bs[kkB][dseg+8]  = bR2;
        *(float4*)&Bs[kkB][dseg+12] = bR3;
        __syncthreads();
        if (s+1 < 32) {
            int off = (s+1)*16;
            aP  = *(const float4*)&Prow[off];
            const float* Rn = Rrow + (size_t)off*Dn;
            bR0 = *(const float4*)&Rn[0];
            bR1 = *(const float4*)&Rn[4];
            bR2 = *(const float4*)&Rn[8];
            bR3 = *(const float4*)&Rn[12];
        }
        #pragma unroll
        for (int kk = 0; kk < 16; kk++) {
            ulonglong2 b01 = *(const ulonglong2*)&Bs[kk][tx*8];
            ulonglong2 b23 = *(const ulonglong2*)&Bs[kk][tx*8+4];
            ulonglong2 a01 = *(const ulonglong2*)&Ad2[kk][ty*8];
            ulonglong2 a23 = *(const ulonglong2*)&Ad2[kk][ty*8+2];
            ulonglong2 a45 = *(const ulonglong2*)&Ad2[kk][ty*8+4];
            ulonglong2 a67 = *(const ulonglong2*)&Ad2[kk][ty*8+6];
            ull bv[4] = {b01.x, b01.y, b23.x, b23.y};
            ull av[8] = {a01.x, a01.y, a23.x, a23.y, a45.x, a45.y, a67.x, a67.y};
            #pragma unroll
            for (int i = 0; i < 8; i++)
                #pragma unroll
                for (int j = 0; j < 4; j++) fma2(acc[i][j], av[i], bv[j]);
        }
    }
    #pragma unroll
    for (int i = 0; i < 8; i++) {
        int eh = ty*8 + i;
        float2* dst = (float2*)&g_prp[(((size_t)ks*Bn + b)*EHn + eh)*Dn + d0base + tx*8];
        #pragma unroll
        for (int j = 0; j < 4; j++) dst[j] = *(float2*)&acc[i][j];
    }
}

// K6a: attn = pr @ Wv + bv (sums k-split partials on load). grid=EH, block=256
__global__ void k6a_attn(const float* __restrict__ Wv, const float* __restrict__ bv) {
    int eh = blockIdx.x, e = eh >> 3, h = eh & 7;
    int t = threadIdx.x, g = t >> 6, c = t & 63;
    __shared__ float ps[Bn][Dn];
    for (int i = t; i < Bn*Dn; i += 256) {
        int b = i >> 9, d = i & 511;
        float s = 0.0f;
        #pragma unroll
        for (int ks = 0; ks < 4; ks++)
            s += g_prp[(((size_t)ks*Bn + b)*EHn + eh)*Dn + d];
        ps[b][d] = s;
    }
    __syncthreads();
    float acc[Bn];
    #pragma unroll
    for (int b = 0; b < Bn; b++) acc[b] = 0.0f;
    const float* W = Wv + (size_t)e*Dn*Dn + h*HDn + c;
    for (int d = g*128; d < g*128+128; d += 4) {
        float w0 = W[(size_t)(d+0)*Dn];
        float w1 = W[(size_t)(d+1)*Dn];
        float w2 = W[(size_t)(d+2)*Dn];
        float w3 = W[(size_t)(d+3)*Dn];
        #pragma unroll
        for (int b = 0; b < Bn; b++) {
            float4 p4 = *(const float4*)&ps[b][d];
            acc[b] = fmaf(p4.x, w0, acc[b]);
            acc[b] = fmaf(p4.y, w1, acc[b]);
            acc[b] = fmaf(p4.z, w2, acc[b]);
            acc[b] = fmaf(p4.w, w3, acc[b]);
        }
    }
    __syncthreads();
    float* red = &ps[0][0];
    #pragma unroll
    for (int b = 0; b < Bn; b++) red[(g*Bn + b)*64 + c] = acc[b];
    __syncthreads();
    for (int i = t; i < Bn*64; i += 256) {
        int b = i >> 6, cc = i & 63;
        float s = red[(0*Bn+b)*64+cc]+red[(1*Bn+b)*64+cc]+red[(2*Bn+b)*64+cc]+red[(3*Bn+b)*64+cc];
        g_attn[(b*En+e)*Dn + h*HDn + cc] = s + bv[e*Dn + h*HDn + cc];
    }
}

// K6b: x = query + attn @ Wo + bo. grid=(8, E), block=256
__global__ void k6b_attnout(const float* __restrict__ Wo, const float* __restrict__ bo,
                            const float* __restrict__ query) {
    int e = blockIdx.y, k0 = blockIdx.x*64;
    int t = threadIdx.x, g = t >> 6, kl = t & 63;
    int k = k0 + kl;
    __shared__ float as_[Bn][Dn];
    for (int i = t; i < Bn*Dn; i += 256) {
        int b = i >> 9, d = i & 511;
        as_[b][d] = g_attn[(b*En+e)*Dn + d];
    }
    __syncthreads();
    float acc[Bn];
    #pragma unroll
    for (int b = 0; b < Bn; b++) acc[b] = 0.0f;
    const float* W = Wo + (size_t)e*Dn*Dn + k;
    for (int d = g*128; d < g*128+128; d += 4) {
        float w0 = W[(size_t)(d+0)*Dn];
        float w1 = W[(size_t)(d+1)*Dn];
        float w2 = W[(size_t)(d+2)*Dn];
        float w3 = W[(size_t)(d+3)*Dn];
        #pragma unroll
        for (int b = 0; b < Bn; b++) {
            float4 a4 = *(const float4*)&as_[b][d];
            acc[b] = fmaf(a4.x, w0, acc[b]);
            acc[b] = fmaf(a4.y, w1, acc[b]);
            acc[b] = fmaf(a4.z, w2, acc[b]);
            acc[b] = fmaf(a4.w, w3, acc[b]);
        }
    }
    __syncthreads();
    float* red = &as_[0][0];
    #pragma unroll
    for (int b = 0; b < Bn; b++) red[(g*Bn + b)*64 + kl] = acc[b];
    __syncthreads();
    for (int i = t; i < Bn*64; i += 256) {
        int b = i >> 6, k2 = i & 63;
        float s = red[(0*Bn+b)*64+k2]+red[(1*Bn+b)*64+k2]+red[(2*Bn+b)*64+k2]+red[(3*Bn+b)*64+k2];
        g_x[(b*En+e)*Dn + k0+k2] = s + bo[e*Dn + k0+k2] + query[b*Dn + k0+k2];
    }
}

// LN of x -> xo. grid=B*E, block=256
__global__ void k_ln2(const float* __restrict__ ln_o_g, const float* __restrict__ ln_o_b) {
    int be = blockIdx.x, e = be & 7;
    int t = threadIdx.x;
    __shared__ float red[256];
    const float* x = g_x + (size_t)be*Dn;
    float v0 = x[t], v1 = x[t+256];
    red[t] = v0 + v1; __syncthreads();
    for (int o = 128; o; o >>= 1) { if (t < o) red[t] += red[t+o]; __syncthreads(); }
    float mu = red[0]*(1.0f/Dn); __syncthreads();
    float d0 = v0-mu, d1 = v1-mu;
    red[t] = d0*d0 + d1*d1; __syncthreads();
    for (int o = 128; o; o >>= 1) { if (t < o) red[t] += red[t+o]; __syncthreads(); }
    float rstd = rsqrtf(red[0]*(1.0f/Dn) + 1e-5f);
    g_xo[be*Dn + t]     = d0*rstd*ln_o_g[e*Dn+t]     + ln_o_b[e*Dn+t];
    g_xo[be*Dn + t+256] = d1*rstd*ln_o_g[e*Dn+t+256] + ln_o_b[e*Dn+t+256];
}

// K7: h = gelu(xo @ W1 + b1). grid=(32, E), block=256
__global__ void k7_ffn1(const float* __restrict__ W1, const float* __restrict__ b1) {
    int e = blockIdx.y, f0 = blockIdx.x*64;
    int t = threadIdx.x, g = t >> 6, fl = t & 63;
    int f = f0 + fl;
    __shared__ float xs[Bn][Dn];
    for (int i = t; i < Bn*Dn; i += 256) {
        int b = i >> 9, d = i & 511;
        xs[b][d] = g_xo[(b*En+e)*Dn + d];
    }
    __syncthreads();
    float acc[Bn];
    #pragma unroll
    for (int b = 0; b < Bn; b++) acc[b] = 0.0f;
    const float* W = W1 + (size_t)e*Dn*Fn + f;
    for (int d = g*128; d < g*128+128; d += 4) {
        float w0 = W[(size_t)(d+0)*Fn];
        float w1 = W[(size_t)(d+1)*Fn];
        float w2 = W[(size_t)(d+2)*Fn];
        float w3 = W[(size_t)(d+3)*Fn];
        #pragma unroll
        for (int b = 0; b < Bn; b++) {
            float4 x4 = *(const float4*)&xs[b][d];
            acc[b] = fmaf(x4.x, w0, acc[b]);
            acc[b] = fmaf(x4.y, w1, acc[b]);
            acc[b] = fmaf(x4.z, w2, acc[b]);
            acc[b] = fmaf(x4.w, w3, acc[b]);
        }
    }
    __syncthreads();
    float* red = &xs[0][0];
    #pragma unroll
    for (int b = 0; b < Bn; b++) red[(g*Bn + b)*64 + fl] = acc[b];
    __syncthreads();
    for (int i = t; i < Bn*64; i += 256) {
        int b = i >> 6, ff = i & 63;
        float v = red[(0*Bn+b)*64+ff]+red[(1*Bn+b)*64+ff]+red[(2*Bn+b)*64+ff]+red[(3*Bn+b)*64+ff]
                + b1[e*Fn + f0+ff];
        v = 0.5f*v*(1.0f + erff(v*0.70710678118654752f));
        g_h[(b*En+e)*Fn + f0+ff] = v;
    }
}

// K8: y partials = h_chunk @ W2_chunk. grid=(8 ktiles, E, 4 fchunk), block=256
__global__ void k8_ffn2(const float* __restrict__ W2) {
    int e = blockIdx.y, k0 = blockIdx.x*64, fc = blockIdx.z;
    int t = threadIdx.x, g = t >> 6, kl = t & 63;
    int k = k0 + kl;
    __shared__ float hs[Bn][512];
    for (int i = t; i < Bn*512; i += 256) {
        int b = i >> 9, f = i & 511;
        hs[b][f] = g_h[(b*En+e)*Fn + fc*512 + f];
    }
    __syncthreads();
    float acc[Bn];
    #pragma unroll
    for (int b = 0; b < Bn; b++) acc[b] = 0.0f;
    const float* W = W2 + (size_t)e*Fn*Dn + ((size_t)fc*512 + g*128)*Dn + k;
    for (int ff = 0; ff < 128; ff += 4) {
        float w0 = W[(size_t)(ff+0)*Dn];
        float w1 = W[(size_t)(ff+1)*Dn];
        float w2 = W[(size_t)(ff+2)*Dn];
        float w3 = W[(size_t)(ff+3)*Dn];
        #pragma unroll
        for (int b = 0; b < Bn; b++) {
            float4 h4 = *(const float4*)&hs[b][g*128 + ff];
            acc[b] = fmaf(h4.x, w0, acc[b]);
            acc[b] = fmaf(h4.y, w1, acc[b]);
            acc[b] = fmaf(h4.z, w2, acc[b]);
            acc[b] = fmaf(h4.w, w3, acc[b]);
        }
    }
    __syncthreads();
    float* red = &hs[0][0];
    #pragma unroll
    for (int b = 0; b < Bn; b++) red[(g*Bn + b)*64 + kl] = acc[b];
    __syncthreads();
    for (int i = t; i < Bn*64; i += 256) {
        int b = i >> 6, kk = i & 63;
        float s = red[(0*Bn+b)*64+kk]+red[(1*Bn+b)*64+kk]+red[(2*Bn+b)*64+kk]+red[(3*Bn+b)*64+kk];
        g_y4[(((size_t)fc*Bn + b)*En + e)*Dn + k0 + kk] = s;
    }
}

// K9: assemble y (= x + b2 + sum partials), reliability weights, mixture. grid=B, block=512
__global__ void k9_final(float* __restrict__ out, const float* __restrict__ b2) {
    int b = blockIdx.x, t = threadIdx.x;
    __shared__ float gt[8];
    if (t < 8) gt[t] = g_gates[b*8+t]*__expf(-0.5f*g_ent[b*8+t]);
    __syncthreads();
    if (t == 0) {
        float s = 0.0f;
        for (int e = 0; e < 8; e++) s += gt[e];
        float inv = 1.0f/(s + 1e-9f);
        for (int e = 0; e < 8; e++) gt[e] *= inv;
    }
    __syncthreads();
    if (t < 8) out[Bn*Dn + Bn*En*Dn + b*8 + t] = gt[t];
    float m = 0.0f;
    #pragma unroll
    for (int e = 0; e < 8; e++) {
        float y = g_x[(b*En+e)*Dn + t] + b2[e*Dn + t];
        #pragma unroll
        for (int fc = 0; fc < 4; fc++)
            y += g_y4[(((size_t)fc*Bn + b)*En + e)*Dn + t];
        out[Bn*Dn + (b*En+e)*Dn + t] = y;
        m = fmaf(gt[e], y, m);
    }
    out[b*Dn + t] = m;   // ALPHA=1 -> fused = mixture
}

extern "C" void kernel_launch(void* const* d_in, const int* in_sizes, int n_in,
                              void* d_out, int out_size) {
    const float* query     = (const float*)d_in[0];
    const float* retrieved = (const float*)d_in[1];
    const float* w_gate    = (const float*)d_in[2];
    const float* ln_q_g    = (const float*)d_in[3];
    const float* ln_q_b    = (const float*)d_in[4];
    const float* Wq        = (const float*)d_in[5];
    const float* bq        = (const float*)d_in[6];
    const float* Wk        = (const float*)d_in[7];
    /* d_in[8] = bk cancels in softmax */
    const float* Wv        = (const float*)d_in[9];
    const float* bv        = (const float*)d_in[10];
    const float* Wo        = (const float*)d_in[11];
    const float* bo        = (const float*)d_in[12];
    const float* ln_o_g    = (const float*)d_in[13];
    const float* ln_o_b    = (const float*)d_in[14];
    const float* W1        = (const float*)d_in[15];
    const float* b1        = (const float*)d_in[16];
    const float* W2        = (const float*)d_in[17];
    const float* b2        = (const float*)d_in[18];
    float* out = (float*)d_out;

    k0_gate_ln<<<Bn, 256>>>(query, w_gate);
    k1_qh<<<dim3(8, En), 256>>>(ln_q_g, ln_q_b, Wq, bq);
    k2_qk<<<EHn, 256>>>(Wk);
    k3_scores<<<dim3(8, Bn), 256>>>(retrieved);
    k4_softmax<<<Bn*En, 256>>>();
    k5_pr<<<dim3(2, Bn, 4), 256>>>(retrieved);
    k6a_attn<<<EHn, 256>>>(Wv, bv);
    k6b_attnout<<<dim3(8, En), 256>>>(Wo, bo, query);
    k_ln2<<<Bn*En, 256>>>(ln_o_g, ln_o_b);
    k7_ffn1<<<dim3(32, En), 256>>>(W1, b1);
    k8_ffn2<<<dim3(8, En, 4), 256>>>(W2);
    k9_final<<<Bn, 512>>>(out, b2);
}

// round 4
// speedup vs baseline: 1.8520x; 1.2534x over previous
#include <cuda_runtime.h>
#include <math.h>

#define Bn 16
#define Ln 2048
#define Dn 512
#define En 8
#define Hn 8
#define HDn 64
#define EHn 64
#define Fn 2048

typedef unsigned long long ull;

// -------- scratch --------
__device__ float g_gates[Bn*En];
__device__ float g_xn[Bn*Dn];
__device__ float g_qhp[4*En*Bn*Dn];        // k1 partials (split over reduction d)
__device__ float g_qk[Bn*EHn*Dn];
__device__ float g_scores[Bn*EHn*Ln];      // 8 MB, becomes probs in place
__device__ float g_ent[Bn*En];
__device__ float g_prp[4*Bn*EHn*Dn];       // k5 partials (split over L)
__device__ float g_attnp[4*En*Bn*Dn];      // k6a partials
__device__ float g_xp[4*En*Bn*Dn];         // k6b partials
__device__ float g_x[Bn*En*Dn];
__device__ float g_xo[Bn*En*Dn];
__device__ float g_h[Bn*En*Fn];
__device__ float g_y4[4*Bn*En*Dn];         // FFN2 f-split partials

__device__ __forceinline__ void fma2(ull &c, ull a, ull b) {
    asm("fma.rn.f32x2 %0, %1, %2, %0;" : "+l"(c) : "l"(a), "l"(b));
}

// K0: gating softmax + normalized query xn. grid=B, block=256
__global__ void k0_gate_ln(const float* __restrict__ query, const float* __restrict__ w_gate) {
    int b = blockIdx.x, t = threadIdx.x;
    __shared__ float q[Dn];
    __shared__ float red[256];
    __shared__ float lred[256*8];
    q[t] = query[b*Dn + t];
    q[t+256] = query[b*Dn + t + 256];
    __syncthreads();
    red[t] = q[t] + q[t+256];
    __syncthreads();
    for (int o = 128; o; o >>= 1) { if (t < o) red[t] += red[t+o]; __syncthreads(); }
    float mu = red[0] * (1.0f/Dn);
    __syncthreads();
    float d0 = q[t] - mu, d1 = q[t+256] - mu;
    red[t] = d0*d0 + d1*d1;
    __syncthreads();
    for (int o = 128; o; o >>= 1) { if (t < o) red[t] += red[t+o]; __syncthreads(); }
    float rstd = rsqrtf(red[0] * (1.0f/Dn) + 1e-5f);
    #pragma unroll
    for (int e = 0; e < 8; e++)
        lred[t*8+e] = q[t]*w_gate[t*8+e] + q[t+256]*w_gate[(t+256)*8+e];
    __syncthreads();
    for (int o = 128; o; o >>= 1) {
        if (t < o) {
            #pragma unroll
            for (int e = 0; e < 8; e++) lred[t*8+e] += lred[(t+o)*8+e];
        }
        __syncthreads();
    }
    if (t == 0) {
        float m = -1e30f;
        for (int e = 0; e < 8; e++) m = fmaxf(m, lred[e]);
        float s = 0.0f, ex[8];
        for (int e = 0; e < 8; e++) { ex[e] = expf(lred[e]-m); s += ex[e]; }
        for (int e = 0; e < 8; e++) g_gates[b*8+e] = ex[e]/s;
    }
    g_xn[b*Dn + t]       = d0*rstd;
    g_xn[b*Dn + t + 256] = d1*rstd;
}

// K1: qh partials. grid=(8 ktiles, E, 4 dsplit), block=256 (4 dgroups x 64 kl)
__global__ void __launch_bounds__(256) k1_qh(const float* __restrict__ ln_q_g,
                      const float* __restrict__ ln_q_b,
                      const float* __restrict__ Wq) {
    int e = blockIdx.y, k0 = blockIdx.x*64, s = blockIdx.z;
    int t = threadIdx.x, g = t >> 6, kl = t & 63;
    __shared__ float sb[4096];            // [0:2048) input tile, then reduce buffer
    float* qn = sb;                        // [16][128]
    for (int i = t; i < Bn*128; i += 256) {
        int b = i >> 7, dd = i & 127;
        int d = s*128 + dd;
        qn[b*128+dd] = g_xn[b*Dn+d]*ln_q_g[e*Dn+d] + ln_q_b[e*Dn+d];
    }
    __syncthreads();
    float acc[Bn];
    #pragma unroll
    for (int b = 0; b < Bn; b++) acc[b] = 0.0f;
    const float* W = Wq + (size_t)e*Dn*Dn + (size_t)(s*128 + g*32)*Dn + k0 + kl;
    #pragma unroll
    for (int d = 0; d < 32; d += 8) {
        float w[8];
        #pragma unroll
        for (int j = 0; j < 8; j++) w[j] = W[(size_t)(d+j)*Dn];
        #pragma unroll
        for (int b = 0; b < Bn; b++) {
            float4 p0 = *(const float4*)&qn[b*128 + g*32 + d];
            float4 p1 = *(const float4*)&qn[b*128 + g*32 + d + 4];
            acc[b] = fmaf(p0.x, w[0], acc[b]); acc[b] = fmaf(p0.y, w[1], acc[b]);
            acc[b] = fmaf(p0.z, w[2], acc[b]); acc[b] = fmaf(p0.w, w[3], acc[b]);
            acc[b] = fmaf(p1.x, w[4], acc[b]); acc[b] = fmaf(p1.y, w[5], acc[b]);
            acc[b] = fmaf(p1.z, w[6], acc[b]); acc[b] = fmaf(p1.w, w[7], acc[b]);
        }
    }
    __syncthreads();
    #pragma unroll
    for (int b = 0; b < Bn; b++) sb[(g*Bn + b)*64 + kl] = acc[b];
    __syncthreads();
    for (int i = t; i < Bn*64; i += 256) {
        int b = i >> 6, k2 = i & 63;
        float v = sb[(0*Bn+b)*64+k2]+sb[(1*Bn+b)*64+k2]+sb[(2*Bn+b)*64+k2]+sb[(3*Bn+b)*64+k2];
        g_qhp[(((size_t)s*En + e)*Bn + b)*Dn + k0 + k2] = v;
    }
}

// K2: qk[b,eh,d] = (sum partials + bq) . Wk row slices, scaled. grid=(EH, 2), block=256
__global__ void __launch_bounds__(256) k2_qk(const float* __restrict__ Wk,
                                             const float* __restrict__ bq) {
    int eh = blockIdx.x, dc = blockIdx.y;
    int e = eh >> 3, h = eh & 7;
    int t = threadIdx.x;
    int d = dc*256 + t;
    __shared__ float qs[Bn][HDn];
    for (int i = t; i < Bn*HDn; i += 256) {
        int b = i >> 6, c = i & 63;
        float v = bq[e*Dn + h*HDn + c];
        #pragma unroll
        for (int s = 0; s < 4; s++)
            v += g_qhp[(((size_t)s*En + e)*Bn + b)*Dn + h*HDn + c];
        qs[b][c] = v;
    }
    __syncthreads();
    const float4* W4 = (const float4*)(Wk + (size_t)e*Dn*Dn + (size_t)d*Dn + h*HDn);
    float acc[Bn];
    #pragma unroll
    for (int b = 0; b < Bn; b++) acc[b] = 0.0f;
    #pragma unroll
    for (int c4 = 0; c4 < 16; c4++) {
        float4 w = W4[c4];
        int c = c4*4;
        #pragma unroll
        for (int b = 0; b < Bn; b++) {
            acc[b] = fmaf(qs[b][c],   w.x, acc[b]);
            acc[b] = fmaf(qs[b][c+1], w.y, acc[b]);
            acc[b] = fmaf(qs[b][c+2], w.z, acc[b]);
            acc[b] = fmaf(qs[b][c+3], w.w, acc[b]);
        }
    }
    #pragma unroll
    for (int b = 0; b < Bn; b++) g_qk[((size_t)b*EHn+eh)*Dn + d] = acc[b]*0.125f;
}

// K3: scores = R @ qk^T per b. Tile 128(l) x 64(eh), K=512, 128 threads, 8x8 micro f32x2.
// grid=(16 ltiles, B). tx=t&15 -> l=tx*8, ty=t>>4 -> eh=ty*8.
__global__ void __launch_bounds__(128, 3) k3_scores(const float* __restrict__ R) {
    int b = blockIdx.y, l0 = blockIdx.x*128;
    int t = threadIdx.x, tx = t & 15, ty = t >> 4;
    __shared__ float As[2][16][132];       // [buf][kk][l]
    __shared__ float2 Bd[2][16][66];       // [buf][kk][eh] duplicated pairs
    ull acc[8][4];
    #pragma unroll
    for (int i = 0; i < 8; i++)
        #pragma unroll
        for (int j = 0; j < 4; j++) acc[i][j] = 0ull;

    int lw = t & 31, kq = t >> 5;          // A loader: rows l0+lw*4+j, cols kq*4
    int ehB = t >> 1, kb = (t & 1)*8;      // B loader
    const float* Ar = R + ((size_t)b*Ln + l0 + lw*4)*Dn + kq*4;
    const float* Br = g_qk + ((size_t)b*EHn + ehB)*Dn + kb;

    float4 a0 = *(const float4*)(Ar + 0*Dn);
    float4 a1 = *(const float4*)(Ar + 1*Dn);
    float4 a2 = *(const float4*)(Ar + 2*Dn);
    float4 a3 = *(const float4*)(Ar + 3*Dn);
    float4 b0 = *(const float4*)(Br);
    float4 b1 = *(const float4*)(Br + 4);

    for (int s = 0; s < 32; s++) {
        int cur = s & 1;
        *(float4*)&As[cur][kq*4+0][lw*4] = make_float4(a0.x, a1.x, a2.x, a3.x);
        *(float4*)&As[cur][kq*4+1][lw*4] = make_float4(a0.y, a1.y, a2.y, a3.y);
        *(float4*)&As[cur][kq*4+2][lw*4] = make_float4(a0.z, a1.z, a2.z, a3.z);
        *(float4*)&As[cur][kq*4+3][lw*4] = make_float4(a0.w, a1.w, a2.w, a3.w);
        Bd[cur][kb+0][ehB] = make_float2(b0.x, b0.x);
        Bd[cur][kb+1][ehB] = make_float2(b0.y, b0.y);
        Bd[cur][kb+2][ehB] = make_float2(b0.z, b0.z);
        Bd[cur][kb+3][ehB] = make_float2(b0.w, b0.w);
        Bd[cur][kb+4][ehB] = make_float2(b1.x, b1.x);
        Bd[cur][kb+5][ehB] = make_float2(b1.y, b1.y);
        Bd[cur][kb+6][ehB] = make_float2(b1.z, b1.z);
        Bd[cur][kb+7][ehB] = make_float2(b1.w, b1.w);
        __syncthreads();
        if (s+1 < 32) {
            const float* An = Ar + (s+1)*16;
            a0 = *(const float4*)(An + 0*Dn);
            a1 = *(const float4*)(An + 1*Dn);
            a2 = *(const float4*)(An + 2*Dn);
            a3 = *(const float4*)(An + 3*Dn);
            const float* Bq = Br + (s+1)*16;
            b0 = *(const float4*)(Bq);
            b1 = *(const float4*)(Bq + 4);
        }
        #pragma unroll
        for (int kk = 0; kk < 16; kk++) {
            ulonglong2 A01 = *(const ulonglong2*)&As[cur][kk][tx*8];
            ulonglong2 A23 = *(const ulonglong2*)&As[cur][kk][tx*8+4];
            ulonglong2 B01 = *(const ulonglong2*)&Bd[cur][kk][ty*8];
            ulonglong2 B23 = *(const ulonglong2*)&Bd[cur][kk][ty*8+2];
            ulonglong2 B45 = *(const ulonglong2*)&Bd[cur][kk][ty*8+4];
            ulonglong2 B67 = *(const ulonglong2*)&Bd[cur][kk][ty*8+6];
            ull av[4] = {A01.x, A01.y, A23.x, A23.y};
            ull bv8[8] = {B01.x, B01.y, B23.x, B23.y, B45.x, B45.y, B67.x, B67.y};
            #pragma unroll
            for (int i = 0; i < 8; i++)
                #pragma unroll
                for (int j = 0; j < 4; j++) fma2(acc[i][j], bv8[i], av[j]);
        }
        __syncthreads();
    }
    #pragma unroll
    for (int i = 0; i < 8; i++) {
        int eh = ty*8 + i;
        float2* dst = (float2*)&g_scores[((size_t)b*EHn + eh)*Ln + l0 + tx*8];
        #pragma unroll
        for (int j = 0; j < 4; j++) dst[j] = *(float2*)&acc[i][j];
    }
}

// K4: softmax per (b,e,h) warp-per-head + entropy. grid=B*E, block=256
__global__ void __launch_bounds__(256) k4_softmax() {
    int be = blockIdx.x;
    int t = threadIdx.x, w = t >> 5, lane = t & 31;
    __shared__ float red[256];
    float* base = g_scores + (size_t)be*Hn*Ln;
    float* src = base + (size_t)w*Ln;
    float4 v[16];
    float m = -1e30f;
    #pragma unroll
    for (int i = 0; i < 16; i++) {
        v[i] = *(const float4*)&src[(i*32 + lane)*4];
        m = fmaxf(m, fmaxf(fmaxf(v[i].x, v[i].y), fmaxf(v[i].z, v[i].w)));
    }
    #pragma unroll
    for (int o = 16; o; o >>= 1) m = fmaxf(m, __shfl_xor_sync(0xffffffffu, m, o));
    float s = 0.0f;
    #pragma unroll
    for (int i = 0; i < 16; i++) {
        v[i].x = __expf(v[i].x - m); v[i].y = __expf(v[i].y - m);
        v[i].z = __expf(v[i].z - m); v[i].w = __expf(v[i].w - m);
        s += v[i].x + v[i].y + v[i].z + v[i].w;
    }
    #pragma unroll
    for (int o = 16; o; o >>= 1) s += __shfl_xor_sync(0xffffffffu, s, o);
    float inv = 1.0f/s;
    #pragma unroll
    for (int i = 0; i < 16; i++) {
        v[i].x *= inv; v[i].y *= inv; v[i].z *= inv; v[i].w *= inv;
        *(float4*)&src[(i*32 + lane)*4] = v[i];
    }
    __syncthreads();
    float lent = 0.0f;
    for (int i = t; i < Ln; i += 256) {
        float s8 = 0.0f;
        #pragma unroll
        for (int h = 0; h < 8; h++) s8 += base[h*Ln + i];
        float p = fmaxf(s8*0.125f, 1e-12f);
        lent -= p*__logf(p);
    }
    red[t] = lent; __syncthreads();
    for (int o = 128; o; o >>= 1) { if (t < o) red[t] += red[t+o]; __syncthreads(); }
    if (t == 0) g_ent[be] = red[0];
}

// K5: pr partial = probs-chunk @ R-chunk. Tile 64(eh) x 128(d), 128 threads, 8x8 micro.
// grid=(4 dtiles, B, 4 ks). tx=t&15 -> d=tx*8, ty=t>>4 -> eh=ty*8.
__global__ void __launch_bounds__(128, 3) k5_pr(const float* __restrict__ R) {
    int b = blockIdx.y, d0 = blockIdx.x*128, ks = blockIdx.z;
    int t = threadIdx.x, tx = t & 15, ty = t >> 4;
    __shared__ float Bs[2][16][132];       // [buf][kk][d]
    __shared__ float2 Ad[2][16][66];       // [buf][kk][eh] duplicated
    ull acc[8][4];
    #pragma unroll
    for (int i = 0; i < 8; i++)
        #pragma unroll
        for (int j = 0; j < 4; j++) acc[i][j] = 0ull;

    int ehA = t >> 1, ka = (t & 1)*8;      // A loader (probs)
    int kkB = t >> 3, dsg = (t & 7)*16;    // B loader (R rows)
    const float* Pr = g_scores + ((size_t)b*EHn + ehA)*Ln + ks*512 + ka;
    const float* Rr = R + ((size_t)b*Ln + ks*512 + kkB)*Dn + d0 + dsg;

    float4 p0 = *(const float4*)(Pr);
    float4 p1 = *(const float4*)(Pr + 4);
    float4 r0 = *(const float4*)(Rr + 0);
    float4 r1 = *(const float4*)(Rr + 4);
    float4 r2 = *(const float4*)(Rr + 8);
    float4 r3 = *(const float4*)(Rr + 12);

    for (int s = 0; s < 32; s++) {
        int cur = s & 1;
        Ad[cur][ka+0][ehA] = make_float2(p0.x, p0.x);
        Ad[cur][ka+1][ehA] = make_float2(p0.y, p0.y);
        Ad[cur][ka+2][ehA] = make_float2(p0.z, p0.z);
        Ad[cur][ka+3][ehA] = make_float2(p0.w, p0.w);
        Ad[cur][ka+4][ehA] = make_float2(p1.x, p1.x);
        Ad[cur][ka+5][ehA] = make_float2(p1.y, p1.y);
        Ad[cur][ka+6][ehA] = make_float2(p1.z, p1.z);
        Ad[cur][ka+7][ehA] = make_float2(p1.w, p1.w);
        *(float4*)&Bs[cur][kkB][dsg+0]  = r0;
        *(float4*)&Bs[cur][kkB][dsg+4]  = r1;
        *(float4*)&Bs[cur][kkB][dsg+8]  = r2;
        *(float4*)&Bs[cur][kkB][dsg+12] = r3;
        __syncthreads();
        if (s+1 < 32) {
            const float* Pn = Pr + (s+1)*16;
            p0 = *(const float4*)(Pn);
            p1 = *(const float4*)(Pn + 4);
            const float* Rn = Rr + (size_t)(s+1)*16*Dn;
            r0 = *(const float4*)(Rn + 0);
            r1 = *(const float4*)(Rn + 4);
            r2 = *(const float4*)(Rn + 8);
            r3 = *(const float4*)(Rn + 12);
        }
        #pragma unroll
        for (int kk = 0; kk < 16; kk++) {
            ulonglong2 B01 = *(const ulonglong2*)&Bs[cur][kk][tx*8];
            ulonglong2 B23 = *(const ulonglong2*)&Bs[cur][kk][tx*8+4];
            ulonglong2 A01 = *(const ulonglong2*)&Ad[cur][kk][ty*8];
            ulonglong2 A23 = *(const ulonglong2*)&Ad[cur][kk][ty*8+2];
            ulonglong2 A45 = *(const ulonglong2*)&Ad[cur][kk][ty*8+4];
            ulonglong2 A67 = *(const ulonglong2*)&Ad[cur][kk][ty*8+6];
            ull bvv[4] = {B01.x, B01.y, B23.x, B23.y};
            ull avv[8] = {A01.x, A01.y, A23.x, A23.y, A45.x, A45.y, A67.x, A67.y};
            #pragma unroll
            for (int i = 0; i < 8; i++)
                #pragma unroll
                for (int j = 0; j < 4; j++) fma2(acc[i][j], avv[i], bvv[j]);
        }
        __syncthreads();
    }
    #pragma unroll
    for (int i = 0; i < 8; i++) {
        int eh = ty*8 + i;
        float2* dst = (float2*)&g_prp[(((size_t)ks*Bn + b)*EHn + eh)*Dn + d0 + tx*8];
        #pragma unroll
        for (int j = 0; j < 4; j++) dst[j] = *(float2*)&acc[i][j];
    }
}

// K6a: attn partials = pr @ Wv (split over d). grid=(EH, 4 s), block=256
__global__ void __launch_bounds__(256) k6a_attn(const float* __restrict__ Wv) {
    int eh = blockIdx.x, s = blockIdx.y;
    int e = eh >> 3, h = eh & 7;
    int t = threadIdx.x, g = t >> 6, c = t & 63;
    __shared__ float sb[4096];
    float* ps = sb;   // [16][128]
    for (int i = t; i < Bn*128; i += 256) {
        int b = i >> 7, dd = i & 127;
        float v = 0.0f;
        #pragma unroll
        for (int ks = 0; ks < 4; ks++)
            v += g_prp[(((size_t)ks*Bn + b)*EHn + eh)*Dn + s*128 + dd];
        ps[b*128+dd] = v;
    }
    __syncthreads();
    float acc[Bn];
    #pragma unroll
    for (int b = 0; b < Bn; b++) acc[b] = 0.0f;
    const float* W = Wv + (size_t)e*Dn*Dn + (size_t)(s*128 + g*32)*Dn + h*HDn + c;
    #pragma unroll
    for (int d = 0; d < 32; d += 8) {
        float w[8];
        #pragma unroll
        for (int j = 0; j < 8; j++) w[j] = W[(size_t)(d+j)*Dn];
        #pragma unroll
        for (int b = 0; b < Bn; b++) {
            float4 q0 = *(const float4*)&ps[b*128 + g*32 + d];
            float4 q1 = *(const float4*)&ps[b*128 + g*32 + d + 4];
            acc[b] = fmaf(q0.x, w[0], acc[b]); acc[b] = fmaf(q0.y, w[1], acc[b]);
            acc[b] = fmaf(q0.z, w[2], acc[b]); acc[b] = fmaf(q0.w, w[3], acc[b]);
            acc[b] = fmaf(q1.x, w[4], acc[b]); acc[b] = fmaf(q1.y, w[5], acc[b]);
            acc[b] = fmaf(q1.z, w[6], acc[b]); acc[b] = fmaf(q1.w, w[7], acc[b]);
        }
    }
    __syncthreads();
    #pragma unroll
    for (int b = 0; b < Bn; b++) sb[(g*Bn + b)*64 + c] = acc[b];
    __syncthreads();
    for (int i = t; i < Bn*64; i += 256) {
        int b = i >> 6, cc = i & 63;
        float v = sb[(0*Bn+b)*64+cc]+sb[(1*Bn+b)*64+cc]+sb[(2*Bn+b)*64+cc]+sb[(3*Bn+b)*64+cc];
        g_attnp[(((size_t)s*En + e)*Bn + b)*Dn + h*HDn + cc] = v;
    }
}

// K6b: x partials = attn @ Wo (split over d). grid=(8, E, 4 s), block=256
__global__ void __launch_bounds__(256) k6b_attnout(const float* __restrict__ Wo,
                                                   const float* __restrict__ bv) {
    int e = blockIdx.y, k0 = blockIdx.x*64, s = blockIdx.z;
    int t = threadIdx.x, g = t >> 6, kl = t & 63;
    __shared__ float sb[4096];
    float* as_ = sb;  // [16][128]
    for (int i = t; i < Bn*128; i += 256) {
        int b = i >> 7, dd = i & 127;
        int d = s*128 + dd;
        float v = bv[e*Dn + d];
        #pragma unroll
        for (int sp = 0; sp < 4; sp++)
            v += g_attnp[(((size_t)sp*En + e)*Bn + b)*Dn + d];
        as_[b*128+dd] = v;
    }
    __syncthreads();
    float acc[Bn];
    #pragma unroll
    for (int b = 0; b < Bn; b++) acc[b] = 0.0f;
    const float* W = Wo + (size_t)e*Dn*Dn + (size_t)(s*128 + g*32)*Dn + k0 + kl;
    #pragma unroll
    for (int d = 0; d < 32; d += 8) {
        float w[8];
        #pragma unroll
        for (int j = 0; j < 8; j++) w[j] = W[(size_t)(d+j)*Dn];
        #pragma unroll
        for (int b = 0; b < Bn; b++) {
            float4 q0 = *(const float4*)&as_[b*128 + g*32 + d];
            float4 q1 = *(const float4*)&as_[b*128 + g*32 + d + 4];
            acc[b] = fmaf(q0.x, w[0], acc[b]); acc[b] = fmaf(q0.y, w[1], acc[b]);
            acc[b] = fmaf(q0.z, w[2], acc[b]); acc[b] = fmaf(q0.w, w[3], acc[b]);
            acc[b] = fmaf(q1.x, w[4], acc[b]); acc[b] = fmaf(q1.y, w[5], acc[b]);
            acc[b] = fmaf(q1.z, w[6], acc[b]); acc[b] = fmaf(q1.w, w[7], acc[b]);
        }
    }
    __syncthreads();
    #pragma unroll
    for (int b = 0; b < Bn; b++) sb[(g*Bn + b)*64 + kl] = acc[b];
    __syncthreads();
    for (int i = t; i < Bn*64; i += 256) {
        int b = i >> 6, k2 = i & 63;
        float v = sb[(0*Bn+b)*64+k2]+sb[(1*Bn+b)*64+k2]+sb[(2*Bn+b)*64+k2]+sb[(3*Bn+b)*64+k2];
        g_xp[(((size_t)s*En + e)*Bn + b)*Dn + k0 + k2] = v;
    }
}

// K_ln2: x = query + bo + sum xp; write g_x and g_xo=LN(x). grid=B*E, block=256
__global__ void __launch_bounds__(256) k_ln2(const float* __restrict__ ln_o_g,
                      const float* __restrict__ ln_o_b,
                      const float* __restrict__ bo, const float* __restrict__ query) {
    int be = blockIdx.x, b = be >> 3, e = be & 7;
    int t = threadIdx.x;
    __shared__ float red[256];
    float v0 = query[b*Dn + t]     + bo[e*Dn + t];
    float v1 = query[b*Dn + t+256] + bo[e*Dn + t+256];
    #pragma unroll
    for (int s = 0; s < 4; s++) {
        v0 += g_xp[(((size_t)s*En + e)*Bn + b)*Dn + t];
        v1 += g_xp[(((size_t)s*En + e)*Bn + b)*Dn + t + 256];
    }
    g_x[be*Dn + t] = v0;
    g_x[be*Dn + t+256] = v1;
    red[t] = v0 + v1; __syncthreads();
    for (int o = 128; o; o >>= 1) { if (t < o) red[t] += red[t+o]; __syncthreads(); }
    float mu = red[0]*(1.0f/Dn); __syncthreads();
    float d0 = v0-mu, d1 = v1-mu;
    red[t] = d0*d0 + d1*d1; __syncthreads();
    for (int o = 128; o; o >>= 1) { if (t < o) red[t] += red[t+o]; __syncthreads(); }
    float rstd = rsqrtf(red[0]*(1.0f/Dn) + 1e-5f);
    g_xo[be*Dn + t]     = d0*rstd*ln_o_g[e*Dn+t]     + ln_o_b[e*Dn+t];
    g_xo[be*Dn + t+256] = d1*rstd*ln_o_g[e*Dn+t+256] + ln_o_b[e*Dn+t+256];
}

// K7: h = gelu(xo @ W1 + b1). grid=(32, E), block=256
__global__ void __launch_bounds__(256) k7_ffn1(const float* __restrict__ W1,
                                               const float* __restrict__ b1) {
    int e = blockIdx.y, f0 = blockIdx.x*64;
    int t = threadIdx.x, g = t >> 6, fl = t & 63;
    int f = f0 + fl;
    __shared__ float xs[Bn][Dn];
    for (int i = t; i < Bn*Dn; i += 256) {
        int b = i >> 9, d = i & 511;
        xs[b][d] = g_xo[(b*En+e)*Dn + d];
    }
    __syncthreads();
    float acc[Bn];
    #pragma unroll
    for (int b = 0; b < Bn; b++) acc[b] = 0.0f;
    const float* W = W1 + (size_t)e*Dn*Fn + (size_t)(g*128)*Fn + f;
    #pragma unroll 4
    for (int d = 0; d < 128; d += 8) {
        float w[8];
        #pragma unroll
        for (int j = 0; j < 8; j++) w[j] = W[(size_t)(d+j)*Fn];
        #pragma unroll
        for (int b = 0; b < Bn; b++) {
            float4 x0 = *(const float4*)&xs[b][g*128 + d];
            float4 x1 = *(const float4*)&xs[b][g*128 + d + 4];
            acc[b] = fmaf(x0.x, w[0], acc[b]); acc[b] = fmaf(x0.y, w[1], acc[b]);
            acc[b] = fmaf(x0.z, w[2], acc[b]); acc[b] = fmaf(x0.w, w[3], acc[b]);
            acc[b] = fmaf(x1.x, w[4], acc[b]); acc[b] = fmaf(x1.y, w[5], acc[b]);
            acc[b] = fmaf(x1.z, w[6], acc[b]); acc[b] = fmaf(x1.w, w[7], acc[b]);
        }
    }
    __syncthreads();
    float* red = &xs[0][0];
    #pragma unroll
    for (int b = 0; b < Bn; b++) red[(g*Bn + b)*64 + fl] = acc[b];
    __syncthreads();
    for (int i = t; i < Bn*64; i += 256) {
        int b = i >> 6, ff = i & 63;
        float v = red[(0*Bn+b)*64+ff]+red[(1*Bn+b)*64+ff]+red[(2*Bn+b)*64+ff]+red[(3*Bn+b)*64+ff]
                + b1[e*Fn + f0+ff];
        v = 0.5f*v*(1.0f + erff(v*0.70710678118654752f));
        g_h[(b*En+e)*Fn + f0+ff] = v;
    }
}

// K8: y partials = h_chunk @ W2_chunk. grid=(8 ktiles, E, 4 fchunk), block=256
__global__ void __launch_bounds__(256) k8_ffn2(const float* __restrict__ W2) {
    int e = blockIdx.y, k0 = blockIdx.x*64, fc = blockIdx.z;
    int t = threadIdx.x, g = t >> 6, kl = t & 63;
    int k = k0 + kl;
    __shared__ float hs[Bn][512];
    for (int i = t; i < Bn*512; i += 256) {
        int b = i >> 9, f = i & 511;
        hs[b][f] = g_h[(b*En+e)*Fn + fc*512 + f];
    }
    __syncthreads();
    float acc[Bn];
    #pragma unroll
    for (int b = 0; b < Bn; b++) acc[b] = 0.0f;
    const float* W = W2 + (size_t)e*Fn*Dn + ((size_t)fc*512 + g*128)*Dn + k;
    #pragma unroll 4
    for (int ff = 0; ff < 128; ff += 8) {
        float w[8];
        #pragma unroll
        for (int j = 0; j < 8; j++) w[j] = W[(size_t)(ff+j)*Dn];
        #pragma unroll
        for (int b = 0; b < Bn; b++) {
            float4 h0 = *(const float4*)&hs[b][g*128 + ff];
            float4 h1 = *(const float4*)&hs[b][g*128 + ff + 4];
            acc[b] = fmaf(h0.x, w[0], acc[b]); acc[b] = fmaf(h0.y, w[1], acc[b]);
            acc[b] = fmaf(h0.z, w[2], acc[b]); acc[b] = fmaf(h0.w, w[3], acc[b]);
            acc[b] = fmaf(h1.x, w[4], acc[b]); acc[b] = fmaf(h1.y, w[5], acc[b]);
            acc[b] = fmaf(h1.z, w[6], acc[b]); acc[b] = fmaf(h1.w, w[7], acc[b]);
        }
    }
    __syncthreads();
    float* red = &hs[0][0];
    #pragma unroll
    for (int b = 0; b < Bn; b++) red[(g*Bn + b)*64 + kl] = acc[b];
    __syncthreads();
    for (int i = t; i < Bn*64; i += 256) {
        int b = i >> 6, kk = i & 63;
        float v = red[(0*Bn+b)*64+kk]+red[(1*Bn+b)*64+kk]+red[(2*Bn+b)*64+kk]+red[(3*Bn+b)*64+kk];
        g_y4[(((size_t)fc*Bn + b)*En + e)*Dn + k0 + kk] = v;
    }
}

// K9: assemble y = x + b2 + sum partials; weights; mixture. grid=B, block=512
__global__ void __launch_bounds__(512) k9_final(float* __restrict__ out,
                                                const float* __restrict__ b2) {
    int b = blockIdx.x, t = threadIdx.x;
    __shared__ float gt[8];
    if (t < 8) gt[t] = g_gates[b*8+t]*__expf(-0.5f*g_ent[b*8+t]);
    __syncthreads();
    if (t == 0) {
        float s = 0.0f;
        for (int e = 0; e < 8; e++) s += gt[e];
        float inv = 1.0f/(s + 1e-9f);
        for (int e = 0; e < 8; e++) gt[e] *= inv;
    }
    __syncthreads();
    if (t < 8) out[Bn*Dn + Bn*En*Dn + b*8 + t] = gt[t];
    float m = 0.0f;
    #pragma unroll
    for (int e = 0; e < 8; e++) {
        float y = g_x[(b*En+e)*Dn + t] + b2[e*Dn + t];
        #pragma unroll
        for (int fc = 0; fc < 4; fc++)
            y += g_y4[(((size_t)fc*Bn + b)*En + e)*Dn + t];
        out[Bn*Dn + (b*En+e)*Dn + t] = y;
        m = fmaf(gt[e], y, m);
    }
    out[b*Dn + t] = m;   // ALPHA=1 -> fused = mixture
}

extern "C" void kernel_launch(void* const* d_in, const int* in_sizes, int n_in,
                              void* d_out, int out_size) {
    const float* query     = (const float*)d_in[0];
    const float* retrieved = (const float*)d_in[1];
    const float* w_gate    = (const float*)d_in[2];
    const float* ln_q_g    = (const float*)d_in[3];
    const float* ln_q_b    = (const float*)d_in[4];
    const float* Wq        = (const float*)d_in[5];
    const float* bq        = (const float*)d_in[6];
    const float* Wk        = (const float*)d_in[7];
    /* d_in[8] = bk cancels in softmax */
    const float* Wv        = (const float*)d_in[9];
    const float* bv        = (const float*)d_in[10];
    const float* Wo        = (const float*)d_in[11];
    const float* bo        = (const float*)d_in[12];
    const float* ln_o_g    = (const float*)d_in[13];
    const float* ln_o_b    = (const float*)d_in[14];
    const float* W1        = (const float*)d_in[15];
    const float* b1        = (const float*)d_in[16];
    const float* W2        = (const float*)d_in[17];
    const float* b2        = (const float*)d_in[18];
    float* out = (float*)d_out;

    k0_gate_ln<<<Bn, 256>>>(query, w_gate);
    k1_qh<<<dim3(8, En, 4), 256>>>(ln_q_g, ln_q_b, Wq);
    k2_qk<<<dim3(EHn, 2), 256>>>(Wk, bq);
    k3_scores<<<dim3(16, Bn), 128>>>(retrieved);
    k4_softmax<<<Bn*En, 256>>>();
    k5_pr<<<dim3(4, Bn, 4), 128>>>(retrieved);
    k6a_attn<<<dim3(EHn, 4), 256>>>(Wv);
    k6b_attnout<<<dim3(8, En, 4), 256>>>(Wo, bv);
    k_ln2<<<Bn*En, 256>>>(ln_o_g, ln_o_b, bo, query);
    k7_ffn1<<<dim3(32, En), 256>>>(W1, b1);
    k8_ffn2<<<dim3(8, En, 4), 256>>>(W2);
    k9_final<<<Bn, 512>>>(out, b2);
}